// round 2
// baseline (speedup 1.0000x reference)
#include <cuda_runtime.h>
#include <cstddef>

// Problem dims (fixed)
#define B_   256
#define T_   512
#define IN_  128
#define H_   256
#define W1_  512
#define W2_  512
#define BT_  (B_ * T_)   // 131072

// ---------------------------------------------------------------------------
// Scratch (device globals — no allocations allowed anywhere)
// ---------------------------------------------------------------------------
__device__ float g_t1[(size_t)BT_ * W1_];   // Phase A layer1 out (reused as aw in Phase C)
__device__ float g_t2[(size_t)BT_ * W2_];   // Phase A layer2 out
__device__ float g_xin[(size_t)BT_ * H_];   // input-MLP output, layout [T, B, H]
__device__ float g_hs [(size_t)BT_ * H_];   // all hidden states,  layout [T, B, H]

// ---------------------------------------------------------------------------
// f32x2 packed helpers (Blackwell sm_100a)
// ---------------------------------------------------------------------------
typedef unsigned long long u64;

__device__ __forceinline__ u64 fma2(u64 a, u64 b, u64 c) {
    u64 d;
    asm("fma.rn.f32x2 %0, %1, %2, %3;" : "=l"(d) : "l"(a), "l"(b), "l"(c));
    return d;
}
__device__ __forceinline__ u64 dup2(float x) {
    u64 d; unsigned int u = __float_as_uint(x);
    asm("mov.b64 %0, {%1, %1};" : "=l"(d) : "r"(u));
    return d;
}
__device__ __forceinline__ void unpack2(u64 v, float& lo, float& hi) {
    unsigned int a, b;
    asm("mov.b64 {%0, %1}, %2;" : "=r"(a), "=r"(b) : "l"(v));
    lo = __uint_as_float(a); hi = __uint_as_float(b);
}

// ---------------------------------------------------------------------------
// Generic fp32 tiled GEMM:  C[M,N] = act(A[M,K] @ W[K,N] + bias (+ Add))
// (verified correct in Round 1 — unchanged)
// ACT: 0 = none, 1 = relu, 2 = tanh
// PERM: output row r = b*T + t is written to row t*B + b (Phase A -> [T,B,H])
// ---------------------------------------------------------------------------
template <int BM, int BN, int BK, int TM, int TN, int ACT, bool PERM, bool ADD>
__global__ void __launch_bounds__((BM / TM) * (BN / TN))
gemm_kernel(const float* __restrict__ A, const float* __restrict__ W,
            const float* __restrict__ bias, const float* __restrict__ Add,
            float* __restrict__ C, int M, int N, int K)
{
    constexpr int THREADS = (BM / TM) * (BN / TN);
    __shared__ float As[BK][BM];
    __shared__ float Bs[BK][BN];

    const int tid  = threadIdx.x;
    const int bcol = blockIdx.x;
    const int brow = blockIdx.y;
    const int tx   = tid % (BN / TN);
    const int ty   = tid / (BN / TN);

    float acc[TM][TN];
#pragma unroll
    for (int i = 0; i < TM; i++)
#pragma unroll
        for (int j = 0; j < TN; j++) acc[i][j] = 0.f;

    const float* Ab = A + (size_t)brow * BM * K;
    const float* Wb = W + (size_t)bcol * BN;

    for (int k0 = 0; k0 < K; k0 += BK) {
#pragma unroll 4
        for (int i = tid * 4; i < BM * BK; i += THREADS * 4) {
            int r = i / BK, c = i % BK;
            float4 v = *(const float4*)(Ab + (size_t)r * K + k0 + c);
            As[c + 0][r] = v.x; As[c + 1][r] = v.y;
            As[c + 2][r] = v.z; As[c + 3][r] = v.w;
        }
#pragma unroll 4
        for (int i = tid * 4; i < BK * BN; i += THREADS * 4) {
            int r = i / BN, c = i % BN;
            float4 v = *(const float4*)(Wb + (size_t)(k0 + r) * N + c);
            *(float4*)&Bs[r][c] = v;
        }
        __syncthreads();

        float ar[TM], br[TN];
#pragma unroll
        for (int kk = 0; kk < BK; kk++) {
#pragma unroll
            for (int i = 0; i < TM; i++) ar[i] = As[kk][ty * TM + i];
#pragma unroll
            for (int j = 0; j < TN; j++) br[j] = Bs[kk][tx * TN + j];
#pragma unroll
            for (int i = 0; i < TM; i++)
#pragma unroll
                for (int j = 0; j < TN; j++) acc[i][j] += ar[i] * br[j];
        }
        __syncthreads();
    }

#pragma unroll
    for (int i = 0; i < TM; i++) {
        int row  = brow * BM + ty * TM + i;
        int orow = row;
        if (PERM) {
            int b = row / T_;
            int t = row - b * T_;
            orow = t * B_ + b;
        }
        float* Crow = C + (size_t)orow * N;
        const float* Arow = ADD ? (Add + (size_t)orow * N) : nullptr;
#pragma unroll
        for (int j = 0; j < TN; j++) {
            int col = bcol * BN + tx * TN + j;
            float v = acc[i][j] + bias[col];
            if (ADD) v += Arow[col];
            if (ACT == 1)      v = fmaxf(v, 0.f);
            else if (ACT == 2) v = tanhf(v);
            Crow[col] = v;
        }
    }
}

// ---------------------------------------------------------------------------
// Phase B: persistent recurrence kernel.
// Grid 64 CTAs x 256 threads. CTA c owns batch rows [4c, 4c+4).
// Activations kept TRANSPOSED in smem: act[k][m], m = 0..3 (16B per k row,
// so an LDS.64 at act[k][0] / act[k][2] yields a packed f32x2 row-pair).
// Weights streamed from L2 each step (2 MB, L2-resident).
// ---------------------------------------------------------------------------
__global__ void __launch_bounds__(256, 1)
recurrence_kernel(const float* __restrict__ w1, const float* __restrict__ b1,
                  const float* __restrict__ w2, const float* __restrict__ b2,
                  const float* __restrict__ w3, const float* __restrict__ b3,
                  const float* __restrict__ xin, float* __restrict__ hs)
{
    __shared__ float hT [H_  * 4];   // h_{t-1} transposed [k][m]
    __shared__ float y1T[W1_ * 4];
    __shared__ float y2T[W2_ * 4];

    const int tid = threadIdx.x;
    const int b0  = blockIdx.x * 4;   // first batch row of this CTA

    // h_{-1} = 0
    for (int i = tid; i < H_ * 4; i += 256) hT[i] = 0.f;
    __syncthreads();

    for (int t = 0; t < T_; t++) {
        // ---- Layer 1: y1[4,512] = relu(h @ w1 + b1), K=256 ----
        {
            const int c0 = tid * 2;
            u64 a00 = 0, a01 = 0, a10 = 0, a11 = 0;  // [rowpair][col]
            const float* Wp = w1 + c0;
#pragma unroll 8
            for (int k = 0; k < H_; k++) {
                u64 r01 = *(const u64*)(hT + k * 4);
                u64 r23 = *(const u64*)(hT + k * 4 + 2);
                float2 w = *(const float2*)(Wp + (size_t)k * W1_);
                u64 wd0 = dup2(w.x), wd1 = dup2(w.y);
                a00 = fma2(r01, wd0, a00);
                a10 = fma2(r23, wd0, a10);
                a01 = fma2(r01, wd1, a01);
                a11 = fma2(r23, wd1, a11);
            }
            float v0, v1, v2, v3;
            float bb0 = b1[c0], bb1 = b1[c0 + 1];
            unpack2(a00, v0, v1); unpack2(a10, v2, v3);
            float4 q0 = { fmaxf(v0 + bb0, 0.f), fmaxf(v1 + bb0, 0.f),
                          fmaxf(v2 + bb0, 0.f), fmaxf(v3 + bb0, 0.f) };
            unpack2(a01, v0, v1); unpack2(a11, v2, v3);
            float4 q1 = { fmaxf(v0 + bb1, 0.f), fmaxf(v1 + bb1, 0.f),
                          fmaxf(v2 + bb1, 0.f), fmaxf(v3 + bb1, 0.f) };
            *(float4*)(y1T + c0 * 4)       = q0;
            *(float4*)(y1T + (c0 + 1) * 4) = q1;
        }
        __syncthreads();

        // ---- Layer 2: y2[4,512] = relu(y1 @ w2 + b2), K=512 ----
        {
            const int c0 = tid * 2;
            u64 a00 = 0, a01 = 0, a10 = 0, a11 = 0;
            const float* Wp = w2 + c0;
#pragma unroll 8
            for (int k = 0; k < W1_; k++) {
                u64 r01 = *(const u64*)(y1T + k * 4);
                u64 r23 = *(const u64*)(y1T + k * 4 + 2);
                float2 w = *(const float2*)(Wp + (size_t)k * W2_);
                u64 wd0 = dup2(w.x), wd1 = dup2(w.y);
                a00 = fma2(r01, wd0, a00);
                a10 = fma2(r23, wd0, a10);
                a01 = fma2(r01, wd1, a01);
                a11 = fma2(r23, wd1, a11);
            }
            float v0, v1, v2, v3;
            float bb0 = b2[c0], bb1 = b2[c0 + 1];
            unpack2(a00, v0, v1); unpack2(a10, v2, v3);
            float4 q0 = { fmaxf(v0 + bb0, 0.f), fmaxf(v1 + bb0, 0.f),
                          fmaxf(v2 + bb0, 0.f), fmaxf(v3 + bb0, 0.f) };
            unpack2(a01, v0, v1); unpack2(a11, v2, v3);
            float4 q1 = { fmaxf(v0 + bb1, 0.f), fmaxf(v1 + bb1, 0.f),
                          fmaxf(v2 + bb1, 0.f), fmaxf(v3 + bb1, 0.f) };
            *(float4*)(y2T + c0 * 4)       = q0;
            *(float4*)(y2T + (c0 + 1) * 4) = q1;
        }
        __syncthreads();

        // ---- Layer 3: h[4,256] = tanh(y2 @ w3 + b3 + xin_t), K=512 ----
        {
            const int c = tid;               // one column per thread (N=256)
            u64 a0 = 0, a1 = 0;
            const float* Wp = w3 + c;
#pragma unroll 8
            for (int k = 0; k < W2_; k++) {
                u64 r01 = *(const u64*)(y2T + k * 4);
                u64 r23 = *(const u64*)(y2T + k * 4 + 2);
                u64 wd  = dup2(Wp[(size_t)k * H_]);
                a0 = fma2(r01, wd, a0);
                a1 = fma2(r23, wd, a1);
            }
            float v0, v1, v2, v3;
            unpack2(a0, v0, v1); unpack2(a1, v2, v3);
            const float bb = b3[c];
            const float* xr = xin + (size_t)t * B_ * H_ + (size_t)b0 * H_ + c;
            float*       hr = hs  + (size_t)t * B_ * H_ + (size_t)b0 * H_ + c;
            v0 = tanhf(v0 + bb + xr[0 * H_]);
            v1 = tanhf(v1 + bb + xr[1 * H_]);
            v2 = tanhf(v2 + bb + xr[2 * H_]);
            v3 = tanhf(v3 + bb + xr[3 * H_]);
            hr[0 * H_] = v0; hr[1 * H_] = v1; hr[2 * H_] = v2; hr[3 * H_] = v3;
            float4 q = { v0, v1, v2, v3 };
            __syncthreads();                 // y2T reads done; hT safe to overwrite
            *(float4*)(hT + c * 4) = q;
        }
        __syncthreads();
    }
}

// ---------------------------------------------------------------------------
// Phase C reduction: online softmax over T (axis 0) + weighted sum of hs.
// ---------------------------------------------------------------------------
__global__ void attn_reduce_kernel(const float* __restrict__ aw,
                                   const float* __restrict__ hs,
                                   float* __restrict__ out)
{
    const int b = blockIdx.x;
    const int h = threadIdx.x;
    float m = -1e30f, s = 0.f, acc = 0.f;
    for (int t = 0; t < T_; t++) {
        size_t idx = ((size_t)t * B_ + b) * H_ + h;
        float a  = aw[idx];
        float hv = hs[idx];
        if (a > m) {
            float c = __expf(m - a);
            s   = s * c + 1.f;
            acc = acc * c + hv;
            m   = a;
        } else {
            float e = __expf(a - m);
            s   += e;
            acc += e * hv;
        }
    }
    out[(size_t)b * H_ + h] = acc / s;
}

// ---------------------------------------------------------------------------
// Launch
// ---------------------------------------------------------------------------
extern "C" void kernel_launch(void* const* d_in, const int* in_sizes, int n_in,
                              void* d_out, int out_size)
{
    const float* x     = (const float*)d_in[0];
    const float* h_w1  = (const float*)d_in[1];
    const float* h_b1  = (const float*)d_in[2];
    const float* h_w2  = (const float*)d_in[3];
    const float* h_b2  = (const float*)d_in[4];
    const float* h_w3  = (const float*)d_in[5];
    const float* h_b3  = (const float*)d_in[6];
    const float* i_w1  = (const float*)d_in[7];
    const float* i_b1  = (const float*)d_in[8];
    const float* i_w2  = (const float*)d_in[9];
    const float* i_b2  = (const float*)d_in[10];
    const float* i_w3  = (const float*)d_in[11];
    const float* i_b3  = (const float*)d_in[12];
    const float* att_w = (const float*)d_in[13];
    const float* att_b = (const float*)d_in[14];
    float* out = (float*)d_out;

    float *t1, *t2, *xin, *hs;
    cudaGetSymbolAddress((void**)&t1,  g_t1);
    cudaGetSymbolAddress((void**)&t2,  g_t2);
    cudaGetSymbolAddress((void**)&xin, g_xin);
    cudaGetSymbolAddress((void**)&hs,  g_hs);
    float* aw = t1;   // reuse t1 for attention logits in Phase C

    // ---------------- Phase A: input MLP over all B*T rows ----------------
    gemm_kernel<128,128,8,8,8, 1,false,false><<<dim3(W1_/128, BT_/128), 256>>>(
        x,  i_w1, i_b1, nullptr, t1,  BT_, W1_, IN_);
    gemm_kernel<128,128,8,8,8, 1,false,false><<<dim3(W2_/128, BT_/128), 256>>>(
        t1, i_w2, i_b2, nullptr, t2,  BT_, W2_, W1_);
    gemm_kernel<128,128,8,8,8, 0,true ,false><<<dim3(H_/128, BT_/128), 256>>>(
        t2, i_w3, i_b3, nullptr, xin, BT_, H_, W2_);

    // ---------------- Phase B: persistent recurrence (ONE launch) ---------
    recurrence_kernel<<<64, 256>>>(h_w1, h_b1, h_w2, h_b2, h_w3, h_b3, xin, hs);

    // ---------------- Phase C: attention pooling --------------------------
    gemm_kernel<128,128,8,8,8, 2,false,false><<<dim3(H_/128, BT_/128), 256>>>(
        hs, att_w, att_b, nullptr, aw, BT_, H_, H_);
    attn_reduce_kernel<<<B_, H_>>>(aw, hs, out);
}

// round 5
// speedup vs baseline: 1.0046x; 1.0046x over previous
#include <cuda_runtime.h>
#include <cstddef>

// Problem dims (fixed)
#define B_   256
#define T_   512
#define IN_  128
#define H_   256
#define W1_  512
#define W2_  512
#define BT_  (B_ * T_)   // 131072

// ---------------------------------------------------------------------------
// Scratch (device globals — no allocations allowed anywhere)
// ---------------------------------------------------------------------------
__device__ float g_t1[(size_t)BT_ * W1_];   // Phase A layer1 out (reused as aw in Phase C)
__device__ float g_t2[(size_t)BT_ * W2_];   // Phase A layer2 out
__device__ float g_xin[(size_t)BT_ * H_];   // input-MLP output, layout [T, B, H]
__device__ float g_hs [(size_t)BT_ * H_];   // all hidden states,  layout [T, B, H]

// ---------------------------------------------------------------------------
// f32x2 packed helpers (Blackwell sm_100a)
// ---------------------------------------------------------------------------
typedef unsigned long long u64;

__device__ __forceinline__ u64 fma2(u64 a, u64 b, u64 c) {
    u64 d;
    asm("fma.rn.f32x2 %0, %1, %2, %3;" : "=l"(d) : "l"(a), "l"(b), "l"(c));
    return d;
}
__device__ __forceinline__ u64 dup2(float x) {
    u64 d; unsigned int u = __float_as_uint(x);
    asm("mov.b64 %0, {%1, %1};" : "=l"(d) : "r"(u));
    return d;
}
__device__ __forceinline__ void unpack2(u64 v, float& lo, float& hi) {
    unsigned int a, b;
    asm("mov.b64 {%0, %1}, %2;" : "=r"(a), "=r"(b) : "l"(v));
    lo = __uint_as_float(a); hi = __uint_as_float(b);
}

// ---------------------------------------------------------------------------
// fp32 tiled GEMM with packed f32x2 compute:
//   C[M,N] = act(A[M,K] @ W[K,N] + bias (+ Add))
// A row-major (K contig), W row-major (N contig).
// ACT: 0 = none, 1 = relu, 2 = tanh
// PERM: output row r = b*T + t is written to row t*B + b (Phase A -> [T,B,H])
// Fixed micro-config: BM=BN=128, BK=16, TM=TN=8, 256 threads.
// ---------------------------------------------------------------------------
template <int ACT, bool PERM, bool ADD>
__global__ void __launch_bounds__(256)
gemm_kernel(const float* __restrict__ A, const float* __restrict__ W,
            const float* __restrict__ bias, const float* __restrict__ Add,
            float* __restrict__ C, int M, int N, int K)
{
    constexpr int BM = 128, BN = 128, BK = 16, TM = 8, TN = 8;
    constexpr int THREADS = 256;
    __shared__ float As[BK][BM];   // A transposed: As[k][m]
    __shared__ float Bs[BK][BN];

    const int tid  = threadIdx.x;
    const int bcol = blockIdx.x;
    const int brow = blockIdx.y;
    const int tx   = tid % (BN / TN);   // 0..15
    const int ty   = tid / (BN / TN);   // 0..15

    u64 acc2[TM][TN / 2];
#pragma unroll
    for (int i = 0; i < TM; i++)
#pragma unroll
        for (int j = 0; j < TN / 2; j++) acc2[i][j] = 0ull;

    const float* Ab = A + (size_t)brow * BM * K;
    const float* Wb = W + (size_t)bcol * BN;

    for (int k0 = 0; k0 < K; k0 += BK) {
        // A tile (BM x BK): float4 along K, stored transposed
#pragma unroll
        for (int i = tid * 4; i < BM * BK; i += THREADS * 4) {
            int r = i / BK, c = i % BK;
            float4 v = *(const float4*)(Ab + (size_t)r * K + k0 + c);
            As[c + 0][r] = v.x; As[c + 1][r] = v.y;
            As[c + 2][r] = v.z; As[c + 3][r] = v.w;
        }
        // W tile (BK x BN): float4 along N
#pragma unroll
        for (int i = tid * 4; i < BK * BN; i += THREADS * 4) {
            int r = i / BN, c = i % BN;
            float4 v = *(const float4*)(Wb + (size_t)(k0 + r) * N + c);
            *(float4*)&Bs[r][c] = v;
        }
        __syncthreads();

#pragma unroll
        for (int kk = 0; kk < BK; kk++) {
            // B fragment first: 8 cols = 4 packed pairs (LDS.128, packs for free)
            ulonglong2 bb0 = *(const ulonglong2*)&Bs[kk][tx * TN];
            ulonglong2 bb1 = *(const ulonglong2*)&Bs[kk][tx * TN + 4];
            u64 bp[TN / 2] = { bb0.x, bb0.y, bb1.x, bb1.y };
            // A fragment: 8 rows, dup'd into packed form
            float4 a0 = *(const float4*)&As[kk][ty * TM];
            float4 a1 = *(const float4*)&As[kk][ty * TM + 4];
            u64 ad[TM];
            ad[0] = dup2(a0.x); ad[1] = dup2(a0.y);
            ad[2] = dup2(a0.z); ad[3] = dup2(a0.w);
            ad[4] = dup2(a1.x); ad[5] = dup2(a1.y);
            ad[6] = dup2(a1.z); ad[7] = dup2(a1.w);
#pragma unroll
            for (int i = 0; i < TM; i++)
#pragma unroll
                for (int j = 0; j < TN / 2; j++)
                    acc2[i][j] = fma2(ad[i], bp[j], acc2[i][j]);
        }
        __syncthreads();
    }

    // Epilogue
#pragma unroll
    for (int i = 0; i < TM; i++) {
        int row  = brow * BM + ty * TM + i;
        int orow = row;
        if (PERM) {              // row = b*T + t  ->  orow = t*B + b
            int b = row / T_;
            int t = row - b * T_;
            orow = t * B_ + b;
        }
        float* Crow = C + (size_t)orow * N;
        const float* Arow = ADD ? (Add + (size_t)orow * N) : nullptr;
#pragma unroll
        for (int j = 0; j < TN / 2; j++) {
            int col = bcol * BN + tx * TN + j * 2;
            float v0, v1;
            unpack2(acc2[i][j], v0, v1);
            v0 += bias[col];
            v1 += bias[col + 1];
            if (ADD) { v0 += Arow[col]; v1 += Arow[col + 1]; }
            if (ACT == 1)      { v0 = fmaxf(v0, 0.f); v1 = fmaxf(v1, 0.f); }
            else if (ACT == 2) { v0 = tanhf(v0);      v1 = tanhf(v1);      }
            Crow[col]     = v0;
            Crow[col + 1] = v1;
        }
    }
}

// ---------------------------------------------------------------------------
// Phase B: persistent recurrence kernel (verified in Round 2).
// Grid 64 CTAs x 256 threads. CTA c owns batch rows [4c, 4c+4).
// Activations kept TRANSPOSED in smem: act[k][m]; LDS.64 yields packed pairs.
// ---------------------------------------------------------------------------
__global__ void __launch_bounds__(256, 1)
recurrence_kernel(const float* __restrict__ w1, const float* __restrict__ b1,
                  const float* __restrict__ w2, const float* __restrict__ b2,
                  const float* __restrict__ w3, const float* __restrict__ b3,
                  const float* __restrict__ xin, float* __restrict__ hs)
{
    __shared__ float hT [H_  * 4];   // h_{t-1} transposed [k][m]
    __shared__ float y1T[W1_ * 4];
    __shared__ float y2T[W2_ * 4];

    const int tid = threadIdx.x;
    const int b0  = blockIdx.x * 4;

    for (int i = tid; i < H_ * 4; i += 256) hT[i] = 0.f;
    __syncthreads();

    for (int t = 0; t < T_; t++) {
        // ---- Layer 1: y1[4,512] = relu(h @ w1 + b1), K=256 ----
        {
            const int c0 = tid * 2;
            u64 a00 = 0, a01 = 0, a10 = 0, a11 = 0;
            const float* Wp = w1 + c0;
#pragma unroll 8
            for (int k = 0; k < H_; k++) {
                u64 r01 = *(const u64*)(hT + k * 4);
                u64 r23 = *(const u64*)(hT + k * 4 + 2);
                float2 w = *(const float2*)(Wp + (size_t)k * W1_);
                u64 wd0 = dup2(w.x), wd1 = dup2(w.y);
                a00 = fma2(r01, wd0, a00);
                a10 = fma2(r23, wd0, a10);
                a01 = fma2(r01, wd1, a01);
                a11 = fma2(r23, wd1, a11);
            }
            float v0, v1, v2, v3;
            float bb0 = b1[c0], bb1 = b1[c0 + 1];
            unpack2(a00, v0, v1); unpack2(a10, v2, v3);
            float4 q0 = { fmaxf(v0 + bb0, 0.f), fmaxf(v1 + bb0, 0.f),
                          fmaxf(v2 + bb0, 0.f), fmaxf(v3 + bb0, 0.f) };
            unpack2(a01, v0, v1); unpack2(a11, v2, v3);
            float4 q1 = { fmaxf(v0 + bb1, 0.f), fmaxf(v1 + bb1, 0.f),
                          fmaxf(v2 + bb1, 0.f), fmaxf(v3 + bb1, 0.f) };
            *(float4*)(y1T + c0 * 4)       = q0;
            *(float4*)(y1T + (c0 + 1) * 4) = q1;
        }
        __syncthreads();

        // ---- Layer 2: y2[4,512] = relu(y1 @ w2 + b2), K=512 ----
        {
            const int c0 = tid * 2;
            u64 a00 = 0, a01 = 0, a10 = 0, a11 = 0;
            const float* Wp = w2 + c0;
#pragma unroll 8
            for (int k = 0; k < W1_; k++) {
                u64 r01 = *(const u64*)(y1T + k * 4);
                u64 r23 = *(const u64*)(y1T + k * 4 + 2);
                float2 w = *(const float2*)(Wp + (size_t)k * W2_);
                u64 wd0 = dup2(w.x), wd1 = dup2(w.y);
                a00 = fma2(r01, wd0, a00);
                a10 = fma2(r23, wd0, a10);
                a01 = fma2(r01, wd1, a01);
                a11 = fma2(r23, wd1, a11);
            }
            float v0, v1, v2, v3;
            float bb0 = b2[c0], bb1 = b2[c0 + 1];
            unpack2(a00, v0, v1); unpack2(a10, v2, v3);
            float4 q0 = { fmaxf(v0 + bb0, 0.f), fmaxf(v1 + bb0, 0.f),
                          fmaxf(v2 + bb0, 0.f), fmaxf(v3 + bb0, 0.f) };
            unpack2(a01, v0, v1); unpack2(a11, v2, v3);
            float4 q1 = { fmaxf(v0 + bb1, 0.f), fmaxf(v1 + bb1, 0.f),
                          fmaxf(v2 + bb1, 0.f), fmaxf(v3 + bb1, 0.f) };
            *(float4*)(y2T + c0 * 4)       = q0;
            *(float4*)(y2T + (c0 + 1) * 4) = q1;
        }
        __syncthreads();

        // ---- Layer 3: h[4,256] = tanh(y2 @ w3 + b3 + xin_t), K=512 ----
        {
            const int c = tid;
            u64 a0 = 0, a1 = 0;
            const float* Wp = w3 + c;
#pragma unroll 8
            for (int k = 0; k < W2_; k++) {
                u64 r01 = *(const u64*)(y2T + k * 4);
                u64 r23 = *(const u64*)(y2T + k * 4 + 2);
                u64 wd  = dup2(Wp[(size_t)k * H_]);
                a0 = fma2(r01, wd, a0);
                a1 = fma2(r23, wd, a1);
            }
            float v0, v1, v2, v3;
            unpack2(a0, v0, v1); unpack2(a1, v2, v3);
            const float bb = b3[c];
            const float* xr = xin + (size_t)t * B_ * H_ + (size_t)b0 * H_ + c;
            float*       hr = hs  + (size_t)t * B_ * H_ + (size_t)b0 * H_ + c;
            v0 = tanhf(v0 + bb + xr[0 * H_]);
            v1 = tanhf(v1 + bb + xr[1 * H_]);
            v2 = tanhf(v2 + bb + xr[2 * H_]);
            v3 = tanhf(v3 + bb + xr[3 * H_]);
            hr[0 * H_] = v0; hr[1 * H_] = v1; hr[2 * H_] = v2; hr[3 * H_] = v3;
            float4 q = { v0, v1, v2, v3 };
            __syncthreads();
            *(float4*)(hT + c * 4) = q;
        }
        __syncthreads();
    }
}

// ---------------------------------------------------------------------------
// Phase C reduction: online softmax over T (axis 0) + weighted sum of hs.
// ---------------------------------------------------------------------------
__global__ void attn_reduce_kernel(const float* __restrict__ aw,
                                   const float* __restrict__ hs,
                                   float* __restrict__ out)
{
    const int b = blockIdx.x;
    const int h = threadIdx.x;
    float m = -1e30f, s = 0.f, acc = 0.f;
    for (int t = 0; t < T_; t++) {
        size_t idx = ((size_t)t * B_ + b) * H_ + h;
        float a  = aw[idx];
        float hv = hs[idx];
        if (a > m) {
            float c = __expf(m - a);
            s   = s * c + 1.f;
            acc = acc * c + hv;
            m   = a;
        } else {
            float e = __expf(a - m);
            s   += e;
            acc += e * hv;
        }
    }
    out[(size_t)b * H_ + h] = acc / s;
}

// ---------------------------------------------------------------------------
// Launch
// ---------------------------------------------------------------------------
extern "C" void kernel_launch(void* const* d_in, const int* in_sizes, int n_in,
                              void* d_out, int out_size)
{
    const float* x     = (const float*)d_in[0];
    const float* h_w1  = (const float*)d_in[1];
    const float* h_b1  = (const float*)d_in[2];
    const float* h_w2  = (const float*)d_in[3];
    const float* h_b2  = (const float*)d_in[4];
    const float* h_w3  = (const float*)d_in[5];
    const float* h_b3  = (const float*)d_in[6];
    const float* i_w1  = (const float*)d_in[7];
    const float* i_b1  = (const float*)d_in[8];
    const float* i_w2  = (const float*)d_in[9];
    const float* i_b2  = (const float*)d_in[10];
    const float* i_w3  = (const float*)d_in[11];
    const float* i_b3  = (const float*)d_in[12];
    const float* att_w = (const float*)d_in[13];
    const float* att_b = (const float*)d_in[14];
    float* out = (float*)d_out;

    float *t1, *t2, *xin, *hs;
    cudaGetSymbolAddress((void**)&t1,  g_t1);
    cudaGetSymbolAddress((void**)&t2,  g_t2);
    cudaGetSymbolAddress((void**)&xin, g_xin);
    cudaGetSymbolAddress((void**)&hs,  g_hs);
    float* aw = t1;   // reuse t1 for attention logits in Phase C

    // ---------------- Phase A: input MLP over all B*T rows ----------------
    gemm_kernel<1,false,false><<<dim3(W1_/128, BT_/128), 256>>>(
        x,  i_w1, i_b1, nullptr, t1,  BT_, W1_, IN_);
    gemm_kernel<1,false,false><<<dim3(W2_/128, BT_/128), 256>>>(
        t1, i_w2, i_b2, nullptr, t2,  BT_, W2_, W1_);
    gemm_kernel<0,true ,false><<<dim3(H_/128, BT_/128), 256>>>(
        t2, i_w3, i_b3, nullptr, xin, BT_, H_, W2_);

    // ---------------- Phase B: persistent recurrence (ONE launch) ---------
    recurrence_kernel<<<64, 256>>>(h_w1, h_b1, h_w2, h_b2, h_w3, h_b3, xin, hs);

    // ---------------- Phase C: attention pooling --------------------------
    gemm_kernel<2,false,false><<<dim3(H_/128, BT_/128), 256>>>(
        hs, att_w, att_b, nullptr, aw, BT_, H_, H_);
    attn_reduce_kernel<<<B_, H_>>>(aw, hs, out);
}

// round 6
// speedup vs baseline: 1.3575x; 1.3512x over previous
#include <cuda_runtime.h>
#include <cstddef>
#include <cstdint>

// Problem dims (fixed)
#define B_   256
#define T_   512
#define IN_  128
#define H_   256
#define W1_  512
#define W2_  512
#define BT_  (B_ * T_)   // 131072

// ---------------------------------------------------------------------------
// Scratch (device globals — no allocations allowed anywhere)
// ---------------------------------------------------------------------------
__device__ float g_t1[(size_t)BT_ * W1_];   // Phase A layer1 out (reused as aw in Phase C)
__device__ float g_t2[(size_t)BT_ * W2_];   // Phase A layer2 out
__device__ float g_xin[(size_t)BT_ * H_];   // input-MLP output, layout [T, B, H]
__device__ float g_hs [(size_t)BT_ * H_];   // all hidden states,  layout [T, B, H]

// ---------------------------------------------------------------------------
// f32x2 packed helpers (Blackwell sm_100a)
// ---------------------------------------------------------------------------
typedef unsigned long long u64;

__device__ __forceinline__ u64 fma2(u64 a, u64 b, u64 c) {
    u64 d;
    asm("fma.rn.f32x2 %0, %1, %2, %3;" : "=l"(d) : "l"(a), "l"(b), "l"(c));
    return d;
}
__device__ __forceinline__ u64 dup2(float x) {
    u64 d; unsigned int u = __float_as_uint(x);
    asm("mov.b64 %0, {%1, %1};" : "=l"(d) : "r"(u));
    return d;
}
__device__ __forceinline__ void unpack2(u64 v, float& lo, float& hi) {
    unsigned int a, b;
    asm("mov.b64 {%0, %1}, %2;" : "=r"(a), "=r"(b) : "l"(v));
    lo = __uint_as_float(a); hi = __uint_as_float(b);
}

// ---------------------------------------------------------------------------
// mbarrier / bulk-async helpers
// ---------------------------------------------------------------------------
__device__ __forceinline__ uint32_t smem_u32(const void* p) {
    uint32_t a;
    asm("{ .reg .u64 t; cvta.to.shared.u64 t, %1; cvt.u32.u64 %0, t; }"
        : "=r"(a) : "l"(p));
    return a;
}
__device__ __forceinline__ void mbar_init(uint32_t mbar, uint32_t count) {
    asm volatile("mbarrier.init.shared.b64 [%0], %1;" :: "r"(mbar), "r"(count) : "memory");
}
__device__ __forceinline__ void mbar_expect_tx(uint32_t mbar, uint32_t bytes) {
    asm volatile("mbarrier.arrive.expect_tx.shared.b64 _, [%0], %1;"
                 :: "r"(mbar), "r"(bytes) : "memory");
}
__device__ __forceinline__ void mbar_wait_parity(uint32_t mbar, uint32_t parity) {
    asm volatile(
        "{\n\t"
        ".reg .pred P;\n\t"
        "WAIT_%=:\n\t"
        "mbarrier.try_wait.parity.shared.b64 P, [%0], %1, 0x989680;\n\t"
        "@P bra.uni DONE_%=;\n\t"
        "bra.uni WAIT_%=;\n\t"
        "DONE_%=:\n\t"
        "}"
        :: "r"(mbar), "r"(parity) : "memory");
}
__device__ __forceinline__ void bulk_g2s(uint32_t dst_smem, const void* src_gmem,
                                         uint32_t bytes, uint32_t mbar) {
    asm volatile(
        "cp.async.bulk.shared::cta.global.mbarrier::complete_tx::bytes [%0], [%1], %2, [%3];"
        :: "r"(dst_smem), "l"(src_gmem), "r"(bytes), "r"(mbar) : "memory");
}

// ---------------------------------------------------------------------------
// fp32 tiled GEMM with packed f32x2 compute (verified Round 5):
//   C[M,N] = act(A[M,K] @ W[K,N] + bias (+ Add))
// ---------------------------------------------------------------------------
template <int ACT, bool PERM, bool ADD>
__global__ void __launch_bounds__(256)
gemm_kernel(const float* __restrict__ A, const float* __restrict__ W,
            const float* __restrict__ bias, const float* __restrict__ Add,
            float* __restrict__ C, int M, int N, int K)
{
    constexpr int BM = 128, BN = 128, BK = 16, TM = 8, TN = 8;
    constexpr int THREADS = 256;
    __shared__ float As[BK][BM];
    __shared__ float Bs[BK][BN];

    const int tid  = threadIdx.x;
    const int bcol = blockIdx.x;
    const int brow = blockIdx.y;
    const int tx   = tid % (BN / TN);
    const int ty   = tid / (BN / TN);

    u64 acc2[TM][TN / 2];
#pragma unroll
    for (int i = 0; i < TM; i++)
#pragma unroll
        for (int j = 0; j < TN / 2; j++) acc2[i][j] = 0ull;

    const float* Ab = A + (size_t)brow * BM * K;
    const float* Wb = W + (size_t)bcol * BN;

    for (int k0 = 0; k0 < K; k0 += BK) {
#pragma unroll
        for (int i = tid * 4; i < BM * BK; i += THREADS * 4) {
            int r = i / BK, c = i % BK;
            float4 v = *(const float4*)(Ab + (size_t)r * K + k0 + c);
            As[c + 0][r] = v.x; As[c + 1][r] = v.y;
            As[c + 2][r] = v.z; As[c + 3][r] = v.w;
        }
#pragma unroll
        for (int i = tid * 4; i < BK * BN; i += THREADS * 4) {
            int r = i / BN, c = i % BN;
            float4 v = *(const float4*)(Wb + (size_t)(k0 + r) * N + c);
            *(float4*)&Bs[r][c] = v;
        }
        __syncthreads();

#pragma unroll
        for (int kk = 0; kk < BK; kk++) {
            ulonglong2 bb0 = *(const ulonglong2*)&Bs[kk][tx * TN];
            ulonglong2 bb1 = *(const ulonglong2*)&Bs[kk][tx * TN + 4];
            u64 bp[TN / 2] = { bb0.x, bb0.y, bb1.x, bb1.y };
            float4 a0 = *(const float4*)&As[kk][ty * TM];
            float4 a1 = *(const float4*)&As[kk][ty * TM + 4];
            u64 ad[TM];
            ad[0] = dup2(a0.x); ad[1] = dup2(a0.y);
            ad[2] = dup2(a0.z); ad[3] = dup2(a0.w);
            ad[4] = dup2(a1.x); ad[5] = dup2(a1.y);
            ad[6] = dup2(a1.z); ad[7] = dup2(a1.w);
#pragma unroll
            for (int i = 0; i < TM; i++)
#pragma unroll
                for (int j = 0; j < TN / 2; j++)
                    acc2[i][j] = fma2(ad[i], bp[j], acc2[i][j]);
        }
        __syncthreads();
    }

#pragma unroll
    for (int i = 0; i < TM; i++) {
        int row  = brow * BM + ty * TM + i;
        int orow = row;
        if (PERM) {
            int b = row / T_;
            int t = row - b * T_;
            orow = t * B_ + b;
        }
        float* Crow = C + (size_t)orow * N;
        const float* Arow = ADD ? (Add + (size_t)orow * N) : nullptr;
#pragma unroll
        for (int j = 0; j < TN / 2; j++) {
            int col = bcol * BN + tx * TN + j * 2;
            float v0, v1;
            unpack2(acc2[i][j], v0, v1);
            v0 += bias[col];
            v1 += bias[col + 1];
            if (ADD) { v0 += Arow[col]; v1 += Arow[col + 1]; }
            if (ACT == 1)      { v0 = fmaxf(v0, 0.f); v1 = fmaxf(v1, 0.f); }
            else if (ACT == 2) { v0 = tanhf(v0);      v1 = tanhf(v1);      }
            Crow[col]     = v0;
            Crow[col + 1] = v1;
        }
    }
}

// ---------------------------------------------------------------------------
// Phase B: persistent recurrence with smem-staged weights.
// 64 CTAs x 256 threads; CTA c owns batch rows [4c, 4c+4).
// Weights streamed in 32KB chunks via cp.async.bulk into a 3-stage smem ring;
// compute reads weights with conflict-free LDS (no L2 latency in the chain).
// Chunk schedule per step (64 chunks, all 8192 floats = 32KB):
//   chunks  0..15 : W1 rows [16j,16j+16) x 512
//   chunks 16..47 : W2 rows [16j,16j+16) x 512
//   chunks 48..63 : W3 rows [32j,32j+32) x 256
// ---------------------------------------------------------------------------
#define NSTAGE      3
#define CHUNK_F     8192           // floats per chunk
#define CHUNK_BYTES (CHUNK_F * 4)  // 32 KB
#define CHUNKS_PER_STEP 64
#define TOTAL_CHUNKS    (T_ * CHUNKS_PER_STEP)

// dynamic smem layout (floats)
#define SM_WBUF 0                          // 3 * 8192
#define SM_HT   (NSTAGE * CHUNK_F)         // 1024
#define SM_Y1T  (SM_HT + H_ * 4)           // 2048
#define SM_Y2T  (SM_Y1T + W1_ * 4)         // 2048
#define SM_B1   (SM_Y2T + W2_ * 4)         // 512
#define SM_B2   (SM_B1 + W1_)              // 512
#define SM_B3   (SM_B2 + W2_)              // 256
#define SM_MBAR (SM_B3 + H_)               // mbarriers (as 2 floats each)
#define SMEM_FLOATS (SM_MBAR + 2 * NSTAGE + 2)
#define SMEM_BYTES  (SMEM_FLOATS * 4)

struct WSrc { const float* w1; const float* w2; const float* w3; };

__device__ __forceinline__ const float* chunk_src(const WSrc& w, int cg) {
    int c = cg & (CHUNKS_PER_STEP - 1);
    if (c < 16)      return w.w1 + (size_t)c * 16 * W1_;
    else if (c < 48) return w.w2 + (size_t)(c - 16) * 16 * W2_;
    else             return w.w3 + (size_t)(c - 48) * 32 * H_;
}

__global__ void __launch_bounds__(256, 1)
recurrence_kernel(const float* __restrict__ w1, const float* __restrict__ b1,
                  const float* __restrict__ w2, const float* __restrict__ b2,
                  const float* __restrict__ w3, const float* __restrict__ b3,
                  const float* __restrict__ xin, float* __restrict__ hs)
{
    extern __shared__ float smem[];
    float* wbuf = smem + SM_WBUF;
    float* hT   = smem + SM_HT;    // h_{t-1} transposed [k][m], m=0..3
    float* y1T  = smem + SM_Y1T;
    float* y2T  = smem + SM_Y2T;
    float* bs1  = smem + SM_B1;
    float* bs2  = smem + SM_B2;
    float* bs3  = smem + SM_B3;
    const uint32_t mbar0 = smem_u32(smem + SM_MBAR);

    const int tid = threadIdx.x;
    const int b0  = blockIdx.x * 4;
    WSrc wsrc = { w1, w2, w3 };

    // init: biases to smem, hT = 0, mbarriers
    for (int i = tid; i < W1_; i += 256) bs1[i] = b1[i];
    for (int i = tid; i < W2_; i += 256) bs2[i] = b2[i];
    for (int i = tid; i < H_;  i += 256) bs3[i] = b3[i];
    for (int i = tid; i < H_ * 4; i += 256) hT[i] = 0.f;
    if (tid == 0) {
#pragma unroll
        for (int s = 0; s < NSTAGE; s++) mbar_init(mbar0 + s * 8, 1);
    }
    __syncthreads();

    // prologue: fill the pipeline
    if (tid == 0) {
#pragma unroll
        for (int s = 0; s < NSTAGE; s++) {
            mbar_expect_tx(mbar0 + s * 8, CHUNK_BYTES);
            bulk_g2s(smem_u32(wbuf + s * CHUNK_F), chunk_src(wsrc, s),
                     CHUNK_BYTES, mbar0 + s * 8);
        }
    }

    int chunk = 0;   // consumer position (uniform across threads)

    for (int t = 0; t < T_; t++) {
        const int c0 = tid * 2;     // 2 columns per thread for N=512 layers

        // ================= Layer 1: y1 = relu(h @ W1 + b1), K=256 ==========
        {
            u64 a00 = 0, a01 = 0, a10 = 0, a11 = 0;
            for (int j = 0; j < 16; j++) {
                const int s = chunk % NSTAGE;
                mbar_wait_parity(mbar0 + s * 8, (chunk / NSTAGE) & 1);
                const float* wb = wbuf + s * CHUNK_F;
#pragma unroll
                for (int kk = 0; kk < 16; kk++) {
                    const int k = j * 16 + kk;
                    u64 r01 = *(const u64*)(hT + k * 4);
                    u64 r23 = *(const u64*)(hT + k * 4 + 2);
                    float2 w = *(const float2*)(wb + kk * W1_ + c0);
                    u64 wd0 = dup2(w.x), wd1 = dup2(w.y);
                    a00 = fma2(r01, wd0, a00);
                    a10 = fma2(r23, wd0, a10);
                    a01 = fma2(r01, wd1, a01);
                    a11 = fma2(r23, wd1, a11);
                }
                __syncthreads();   // all threads done with buffer s
                if (tid == 0 && chunk + NSTAGE < TOTAL_CHUNKS) {
                    const int nc = chunk + NSTAGE;
                    const int ns = nc % NSTAGE;
                    mbar_expect_tx(mbar0 + ns * 8, CHUNK_BYTES);
                    bulk_g2s(smem_u32(wbuf + ns * CHUNK_F), chunk_src(wsrc, nc),
                             CHUNK_BYTES, mbar0 + ns * 8);
                }
                chunk++;
            }
            float v0, v1, v2, v3;
            const float bb0 = bs1[c0], bb1 = bs1[c0 + 1];
            unpack2(a00, v0, v1); unpack2(a10, v2, v3);
            float4 q0 = { fmaxf(v0 + bb0, 0.f), fmaxf(v1 + bb0, 0.f),
                          fmaxf(v2 + bb0, 0.f), fmaxf(v3 + bb0, 0.f) };
            unpack2(a01, v0, v1); unpack2(a11, v2, v3);
            float4 q1 = { fmaxf(v0 + bb1, 0.f), fmaxf(v1 + bb1, 0.f),
                          fmaxf(v2 + bb1, 0.f), fmaxf(v3 + bb1, 0.f) };
            *(float4*)(y1T + c0 * 4)       = q0;
            *(float4*)(y1T + (c0 + 1) * 4) = q1;
        }
        __syncthreads();

        // ================= Layer 2: y2 = relu(y1 @ W2 + b2), K=512 =========
        {
            u64 a00 = 0, a01 = 0, a10 = 0, a11 = 0;
            for (int j = 0; j < 32; j++) {
                const int s = chunk % NSTAGE;
                mbar_wait_parity(mbar0 + s * 8, (chunk / NSTAGE) & 1);
                const float* wb = wbuf + s * CHUNK_F;
#pragma unroll
                for (int kk = 0; kk < 16; kk++) {
                    const int k = j * 16 + kk;
                    u64 r01 = *(const u64*)(y1T + k * 4);
                    u64 r23 = *(const u64*)(y1T + k * 4 + 2);
                    float2 w = *(const float2*)(wb + kk * W2_ + c0);
                    u64 wd0 = dup2(w.x), wd1 = dup2(w.y);
                    a00 = fma2(r01, wd0, a00);
                    a10 = fma2(r23, wd0, a10);
                    a01 = fma2(r01, wd1, a01);
                    a11 = fma2(r23, wd1, a11);
                }
                __syncthreads();
                if (tid == 0 && chunk + NSTAGE < TOTAL_CHUNKS) {
                    const int nc = chunk + NSTAGE;
                    const int ns = nc % NSTAGE;
                    mbar_expect_tx(mbar0 + ns * 8, CHUNK_BYTES);
                    bulk_g2s(smem_u32(wbuf + ns * CHUNK_F), chunk_src(wsrc, nc),
                             CHUNK_BYTES, mbar0 + ns * 8);
                }
                chunk++;
            }
            float v0, v1, v2, v3;
            const float bb0 = bs2[c0], bb1 = bs2[c0 + 1];
            unpack2(a00, v0, v1); unpack2(a10, v2, v3);
            float4 q0 = { fmaxf(v0 + bb0, 0.f), fmaxf(v1 + bb0, 0.f),
                          fmaxf(v2 + bb0, 0.f), fmaxf(v3 + bb0, 0.f) };
            unpack2(a01, v0, v1); unpack2(a11, v2, v3);
            float4 q1 = { fmaxf(v0 + bb1, 0.f), fmaxf(v1 + bb1, 0.f),
                          fmaxf(v2 + bb1, 0.f), fmaxf(v3 + bb1, 0.f) };
            *(float4*)(y2T + c0 * 4)       = q0;
            *(float4*)(y2T + (c0 + 1) * 4) = q1;
        }
        __syncthreads();

        // ========== Layer 3: h = tanh(y2 @ W3 + b3 + xin_t), K=512 =========
        {
            const int c = tid;   // one column per thread (N=256)
            u64 a0 = 0, a1 = 0;
            for (int j = 0; j < 16; j++) {
                const int s = chunk % NSTAGE;
                mbar_wait_parity(mbar0 + s * 8, (chunk / NSTAGE) & 1);
                const float* wb = wbuf + s * CHUNK_F;
#pragma unroll
                for (int kk = 0; kk < 32; kk++) {
                    const int k = j * 32 + kk;
                    u64 r01 = *(const u64*)(y2T + k * 4);
                    u64 r23 = *(const u64*)(y2T + k * 4 + 2);
                    u64 wd  = dup2(wb[kk * H_ + c]);
                    a0 = fma2(r01, wd, a0);
                    a1 = fma2(r23, wd, a1);
                }
                __syncthreads();
                if (tid == 0 && chunk + NSTAGE < TOTAL_CHUNKS) {
                    const int nc = chunk + NSTAGE;
                    const int ns = nc % NSTAGE;
                    mbar_expect_tx(mbar0 + ns * 8, CHUNK_BYTES);
                    bulk_g2s(smem_u32(wbuf + ns * CHUNK_F), chunk_src(wsrc, nc),
                             CHUNK_BYTES, mbar0 + ns * 8);
                }
                chunk++;
            }
            float v0, v1, v2, v3;
            unpack2(a0, v0, v1); unpack2(a1, v2, v3);
            const float bb = bs3[c];
            const float* xr = xin + (size_t)t * B_ * H_ + (size_t)b0 * H_ + c;
            float*       hr = hs  + (size_t)t * B_ * H_ + (size_t)b0 * H_ + c;
            v0 = tanhf(v0 + bb + xr[0 * H_]);
            v1 = tanhf(v1 + bb + xr[1 * H_]);
            v2 = tanhf(v2 + bb + xr[2 * H_]);
            v3 = tanhf(v3 + bb + xr[3 * H_]);
            hr[0 * H_] = v0; hr[1 * H_] = v1; hr[2 * H_] = v2; hr[3 * H_] = v3;
            float4 q = { v0, v1, v2, v3 };
            __syncthreads();   // all layer-3 reads of y2T/hT done
            *(float4*)(hT + c * 4) = q;
        }
        __syncthreads();
    }
}

// ---------------------------------------------------------------------------
// Phase C reduction: online softmax over T (axis 0) + weighted sum of hs.
// ---------------------------------------------------------------------------
__global__ void attn_reduce_kernel(const float* __restrict__ aw,
                                   const float* __restrict__ hs,
                                   float* __restrict__ out)
{
    const int b = blockIdx.x;
    const int h = threadIdx.x;
    float m = -1e30f, s = 0.f, acc = 0.f;
    for (int t = 0; t < T_; t++) {
        size_t idx = ((size_t)t * B_ + b) * H_ + h;
        float a  = aw[idx];
        float hv = hs[idx];
        if (a > m) {
            float c = __expf(m - a);
            s   = s * c + 1.f;
            acc = acc * c + hv;
            m   = a;
        } else {
            float e = __expf(a - m);
            s   += e;
            acc += e * hv;
        }
    }
    out[(size_t)b * H_ + h] = acc / s;
}

// ---------------------------------------------------------------------------
// Launch
// ---------------------------------------------------------------------------
extern "C" void kernel_launch(void* const* d_in, const int* in_sizes, int n_in,
                              void* d_out, int out_size)
{
    const float* x     = (const float*)d_in[0];
    const float* h_w1  = (const float*)d_in[1];
    const float* h_b1  = (const float*)d_in[2];
    const float* h_w2  = (const float*)d_in[3];
    const float* h_b2  = (const float*)d_in[4];
    const float* h_w3  = (const float*)d_in[5];
    const float* h_b3  = (const float*)d_in[6];
    const float* i_w1  = (const float*)d_in[7];
    const float* i_b1  = (const float*)d_in[8];
    const float* i_w2  = (const float*)d_in[9];
    const float* i_b2  = (const float*)d_in[10];
    const float* i_w3  = (const float*)d_in[11];
    const float* i_b3  = (const float*)d_in[12];
    const float* att_w = (const float*)d_in[13];
    const float* att_b = (const float*)d_in[14];
    float* out = (float*)d_out;

    float *t1, *t2, *xin, *hs;
    cudaGetSymbolAddress((void**)&t1,  g_t1);
    cudaGetSymbolAddress((void**)&t2,  g_t2);
    cudaGetSymbolAddress((void**)&xin, g_xin);
    cudaGetSymbolAddress((void**)&hs,  g_hs);
    float* aw = t1;   // reuse t1 for attention logits in Phase C

    // ---------------- Phase A: input MLP over all B*T rows ----------------
    gemm_kernel<1,false,false><<<dim3(W1_/128, BT_/128), 256>>>(
        x,  i_w1, i_b1, nullptr, t1,  BT_, W1_, IN_);
    gemm_kernel<1,false,false><<<dim3(W2_/128, BT_/128), 256>>>(
        t1, i_w2, i_b2, nullptr, t2,  BT_, W2_, W1_);
    gemm_kernel<0,true ,false><<<dim3(H_/128, BT_/128), 256>>>(
        t2, i_w3, i_b3, nullptr, xin, BT_, H_, W2_);

    // ---------------- Phase B: persistent recurrence (ONE launch) ---------
    cudaFuncSetAttribute(recurrence_kernel,
                         cudaFuncAttributeMaxDynamicSharedMemorySize, SMEM_BYTES);
    recurrence_kernel<<<64, 256, SMEM_BYTES>>>(
        h_w1, h_b1, h_w2, h_b2, h_w3, h_b3, xin, hs);

    // ---------------- Phase C: attention pooling --------------------------
    gemm_kernel<2,false,false><<<dim3(H_/128, BT_/128), 256>>>(
        hs, att_w, att_b, nullptr, aw, BT_, H_, H_);
    attn_reduce_kernel<<<B_, H_>>>(aw, hs, out);
}

// round 8
// speedup vs baseline: 1.4431x; 1.0631x over previous
#include <cuda_runtime.h>
#include <cstddef>
#include <cstdint>

// Problem dims (fixed)
#define B_   256
#define T_   512
#define IN_  128
#define H_   256
#define W1_  512
#define W2_  512
#define BT_  (B_ * T_)   // 131072

// ---------------------------------------------------------------------------
// Scratch (device globals — no allocations allowed anywhere)
// ---------------------------------------------------------------------------
__device__ float g_t1[(size_t)BT_ * W1_];   // Phase A layer1 out (reused as aw in Phase C)
__device__ float g_t2[(size_t)BT_ * W2_];   // Phase A layer2 out
__device__ float g_xin[(size_t)BT_ * H_];   // input-MLP output, layout [T, B, H]
__device__ float g_hs [(size_t)BT_ * H_];   // all hidden states,  layout [T, B, H]

// ---------------------------------------------------------------------------
// f32x2 packed helpers (Blackwell sm_100a)
// ---------------------------------------------------------------------------
typedef unsigned long long u64;

__device__ __forceinline__ u64 fma2(u64 a, u64 b, u64 c) {
    u64 d;
    asm("fma.rn.f32x2 %0, %1, %2, %3;" : "=l"(d) : "l"(a), "l"(b), "l"(c));
    return d;
}
__device__ __forceinline__ u64 dup2(float x) {
    u64 d; unsigned int u = __float_as_uint(x);
    asm("mov.b64 %0, {%1, %1};" : "=l"(d) : "r"(u));
    return d;
}
__device__ __forceinline__ void unpack2(u64 v, float& lo, float& hi) {
    unsigned int a, b;
    asm("mov.b64 {%0, %1}, %2;" : "=r"(a), "=r"(b) : "l"(v));
    lo = __uint_as_float(a); hi = __uint_as_float(b);
}

// ---------------------------------------------------------------------------
// mbarrier / bulk-async / cluster helpers
// ---------------------------------------------------------------------------
__device__ __forceinline__ uint32_t smem_u32(const void* p) {
    uint32_t a;
    asm("{ .reg .u64 t; cvta.to.shared.u64 t, %1; cvt.u32.u64 %0, t; }"
        : "=r"(a) : "l"(p));
    return a;
}
__device__ __forceinline__ void mbar_init(uint32_t mbar, uint32_t count) {
    asm volatile("mbarrier.init.shared.b64 [%0], %1;" :: "r"(mbar), "r"(count) : "memory");
}
__device__ __forceinline__ void mbar_expect_tx(uint32_t mbar, uint32_t bytes) {
    asm volatile("mbarrier.arrive.expect_tx.shared.b64 _, [%0], %1;"
                 :: "r"(mbar), "r"(bytes) : "memory");
}
__device__ __forceinline__ void mbar_wait_parity(uint32_t mbar, uint32_t parity) {
    asm volatile(
        "{\n\t"
        ".reg .pred P;\n\t"
        "WAIT_%=:\n\t"
        "mbarrier.try_wait.parity.shared.b64 P, [%0], %1, 0x989680;\n\t"
        "@P bra.uni DONE_%=;\n\t"
        "bra.uni WAIT_%=;\n\t"
        "DONE_%=:\n\t"
        "}"
        :: "r"(mbar), "r"(parity) : "memory");
}
__device__ __forceinline__ uint32_t mapa_rank(uint32_t addr, uint32_t rank) {
    uint32_t r;
    asm("mapa.shared::cluster.u32 %0, %1, %2;" : "=r"(r) : "r"(addr), "r"(rank));
    return r;
}
__device__ __forceinline__ void mbar_arrive_remote(uint32_t cluster_addr) {
    asm volatile("mbarrier.arrive.shared::cluster.b64 _, [%0];"
                 :: "r"(cluster_addr) : "memory");
}
// Multicast bulk copy: data + complete_tx delivered to the same smem offset /
// barrier offset in every CTA whose bit is set in mask.
__device__ __forceinline__ void bulk_g2s_mc(uint32_t dst_smem, const void* src_gmem,
                                            uint32_t bytes, uint32_t mbar, uint16_t mask) {
    asm volatile(
        "cp.async.bulk.shared::cluster.global.mbarrier::complete_tx::bytes.multicast::cluster "
        "[%0], [%1], %2, [%3], %4;"
        :: "r"(dst_smem), "l"(src_gmem), "r"(bytes), "r"(mbar), "h"(mask) : "memory");
}
__device__ __forceinline__ uint32_t cluster_rank() {
    uint32_t r; asm("mov.u32 %0, %%cluster_ctarank;" : "=r"(r)); return r;
}
#define CLUSTER_SYNC() do { \
    asm volatile("barrier.cluster.arrive.aligned;" ::: "memory"); \
    asm volatile("barrier.cluster.wait.aligned;"   ::: "memory"); \
} while (0)

// ---------------------------------------------------------------------------
// fp32 tiled GEMM with packed f32x2 compute (verified Rounds 5-6):
//   C[M,N] = act(A[M,K] @ W[K,N] + bias (+ Add))
// ---------------------------------------------------------------------------
template <int ACT, bool PERM, bool ADD>
__global__ void __launch_bounds__(256)
gemm_kernel(const float* __restrict__ A, const float* __restrict__ W,
            const float* __restrict__ bias, const float* __restrict__ Add,
            float* __restrict__ C, int M, int N, int K)
{
    constexpr int BM = 128, BN = 128, BK = 16, TM = 8, TN = 8;
    constexpr int THREADS = 256;
    __shared__ float As[BK][BM];
    __shared__ float Bs[BK][BN];

    const int tid  = threadIdx.x;
    const int bcol = blockIdx.x;
    const int brow = blockIdx.y;
    const int tx   = tid % (BN / TN);
    const int ty   = tid / (BN / TN);

    u64 acc2[TM][TN / 2];
#pragma unroll
    for (int i = 0; i < TM; i++)
#pragma unroll
        for (int j = 0; j < TN / 2; j++) acc2[i][j] = 0ull;

    const float* Ab = A + (size_t)brow * BM * K;
    const float* Wb = W + (size_t)bcol * BN;

    for (int k0 = 0; k0 < K; k0 += BK) {
#pragma unroll
        for (int i = tid * 4; i < BM * BK; i += THREADS * 4) {
            int r = i / BK, c = i % BK;
            float4 v = *(const float4*)(Ab + (size_t)r * K + k0 + c);
            As[c + 0][r] = v.x; As[c + 1][r] = v.y;
            As[c + 2][r] = v.z; As[c + 3][r] = v.w;
        }
#pragma unroll
        for (int i = tid * 4; i < BK * BN; i += THREADS * 4) {
            int r = i / BN, c = i % BN;
            float4 v = *(const float4*)(Wb + (size_t)(k0 + r) * N + c);
            *(float4*)&Bs[r][c] = v;
        }
        __syncthreads();

#pragma unroll
        for (int kk = 0; kk < BK; kk++) {
            ulonglong2 bb0 = *(const ulonglong2*)&Bs[kk][tx * TN];
            ulonglong2 bb1 = *(const ulonglong2*)&Bs[kk][tx * TN + 4];
            u64 bp[TN / 2] = { bb0.x, bb0.y, bb1.x, bb1.y };
            float4 a0 = *(const float4*)&As[kk][ty * TM];
            float4 a1 = *(const float4*)&As[kk][ty * TM + 4];
            u64 ad[TM];
            ad[0] = dup2(a0.x); ad[1] = dup2(a0.y);
            ad[2] = dup2(a0.z); ad[3] = dup2(a0.w);
            ad[4] = dup2(a1.x); ad[5] = dup2(a1.y);
            ad[6] = dup2(a1.z); ad[7] = dup2(a1.w);
#pragma unroll
            for (int i = 0; i < TM; i++)
#pragma unroll
                for (int j = 0; j < TN / 2; j++)
                    acc2[i][j] = fma2(ad[i], bp[j], acc2[i][j]);
        }
        __syncthreads();
    }

#pragma unroll
    for (int i = 0; i < TM; i++) {
        int row  = brow * BM + ty * TM + i;
        int orow = row;
        if (PERM) {
            int b = row / T_;
            int t = row - b * T_;
            orow = t * B_ + b;
        }
        float* Crow = C + (size_t)orow * N;
        const float* Arow = ADD ? (Add + (size_t)orow * N) : nullptr;
#pragma unroll
        for (int j = 0; j < TN / 2; j++) {
            int col = bcol * BN + tx * TN + j * 2;
            float v0, v1;
            unpack2(acc2[i][j], v0, v1);
            v0 += bias[col];
            v1 += bias[col + 1];
            if (ADD) { v0 += Arow[col]; v1 += Arow[col + 1]; }
            if (ACT == 1)      { v0 = fmaxf(v0, 0.f); v1 = fmaxf(v1, 0.f); }
            else if (ACT == 2) { v0 = tanhf(v0);      v1 = tanhf(v1);      }
            Crow[col]     = v0;
            Crow[col + 1] = v1;
        }
    }
}

// ---------------------------------------------------------------------------
// Phase B: persistent recurrence, 128 CTAs x 256 threads, clusters of 4.
// CTA c owns batch rows [2c, 2c+2). Weights streamed in 32KB chunks via
// MULTICAST cp.async.bulk: rank s produces stage s (NSTAGE=4), one L2 read
// serves all 4 CTAs. full[s]: per-CTA, count 1, re-armed by local expect_tx.
// empty[s]: on rank s, count 4; consumers remote-arrive after consuming.
// Chunk schedule per step (64 chunks x 8192 floats):
//   chunks  0..15 : W1 rows [16j,16j+16) x 512
//   chunks 16..47 : W2 rows [16j,16j+16) x 512
//   chunks 48..63 : W3 rows [32j,32j+32) x 256
// ---------------------------------------------------------------------------
#define NSTAGE      4
#define CHUNK_F     8192
#define CHUNK_BYTES (CHUNK_F * 4)
#define CHUNKS_PER_STEP 64
#define TOTAL_CHUNKS    (T_ * CHUNKS_PER_STEP)
#define MC_MASK     0xFu

// dynamic smem layout (floats)
#define SM_WBUF  0
#define SM_HT    (NSTAGE * CHUNK_F)          // 512  (H_ * 2)
#define SM_Y1T   (SM_HT + H_ * 2)            // 1024 (W1_ * 2)
#define SM_Y2T   (SM_Y1T + W1_ * 2)          // 1024
#define SM_B1    (SM_Y2T + W2_ * 2)          // 512
#define SM_B2    (SM_B1 + W1_)               // 512
#define SM_B3    (SM_B2 + W2_)               // 256
#define SM_FULL  (SM_B3 + H_)                // 4 mbarriers (2 floats each)
#define SM_EMPTY (SM_FULL + 2 * NSTAGE)
#define SMEM_FLOATS (SM_EMPTY + 2 * NSTAGE)
#define SMEM_BYTES  (SMEM_FLOATS * 4)

struct WSrc { const float* w1; const float* w2; const float* w3; };

__device__ __forceinline__ const float* chunk_src(const WSrc& w, int cg) {
    int c = cg & (CHUNKS_PER_STEP - 1);
    if (c < 16)      return w.w1 + (size_t)c * 16 * W1_;
    else if (c < 48) return w.w2 + (size_t)(c - 16) * 16 * W2_;
    else             return w.w3 + (size_t)(c - 48) * 32 * H_;
}

__global__ void __launch_bounds__(256, 1) __cluster_dims__(4, 1, 1)
recurrence_kernel(const float* __restrict__ w1, const float* __restrict__ b1,
                  const float* __restrict__ w2, const float* __restrict__ b2,
                  const float* __restrict__ w3, const float* __restrict__ b3,
                  const float* __restrict__ xin, float* __restrict__ hs)
{
    extern __shared__ float smem[];
    float* wbuf = smem + SM_WBUF;
    float* hT   = smem + SM_HT;    // act transposed: [k][m], m = 0..1
    float* y1T  = smem + SM_Y1T;
    float* y2T  = smem + SM_Y2T;
    float* bs1  = smem + SM_B1;
    float* bs2  = smem + SM_B2;
    float* bs3  = smem + SM_B3;
    const uint32_t fullb  = smem_u32(smem + SM_FULL);
    const uint32_t emptyb = smem_u32(smem + SM_EMPTY);

    const int tid = threadIdx.x;
    const int b0  = blockIdx.x * 2;    // first batch row of this CTA
    const uint32_t rank = cluster_rank();
    WSrc wsrc = { w1, w2, w3 };

    for (int i = tid; i < W1_; i += 256) bs1[i] = b1[i];
    for (int i = tid; i < W2_; i += 256) bs2[i] = b2[i];
    for (int i = tid; i < H_;  i += 256) bs3[i] = b3[i];
    for (int i = tid; i < H_ * 2; i += 256) hT[i] = 0.f;
    if (tid == 0) {
#pragma unroll
        for (int s = 0; s < NSTAGE; s++) {
            mbar_init(fullb  + s * 8, 1);
            mbar_init(emptyb + s * 8, NSTAGE);   // 4 consumer arrivals
        }
    }
    __syncthreads();

    // prologue: arm all full barriers, cluster-sync, each rank produces its stage
    if (tid == 0) {
#pragma unroll
        for (int s = 0; s < NSTAGE; s++) mbar_expect_tx(fullb + s * 8, CHUNK_BYTES);
    }
    CLUSTER_SYNC();
    if (tid == 0) {
        bulk_g2s_mc(smem_u32(wbuf + rank * CHUNK_F), chunk_src(wsrc, (int)rank),
                    CHUNK_BYTES, fullb + rank * 8, MC_MASK);
    }

    int chunk = 0;   // uniform consumer position

    // bookkeeping after consuming `chunk` (stage s): re-arm full, signal empty,
    // and (if producer) refill the stage with chunk+NSTAGE.
#define CHUNK_BOOKKEEP()                                                        \
    do {                                                                        \
        __syncthreads();                                                        \
        if (tid == 0 && chunk + NSTAGE < TOTAL_CHUNKS) {                        \
            const int s_ = chunk & (NSTAGE - 1);                                \
            mbar_expect_tx(fullb + s_ * 8, CHUNK_BYTES);                        \
            mbar_arrive_remote(mapa_rank(emptyb + s_ * 8, (uint32_t)s_));       \
            if (rank == (uint32_t)s_) {                                         \
                mbar_wait_parity(emptyb + s_ * 8, (chunk >> 2) & 1);            \
                bulk_g2s_mc(smem_u32(wbuf + s_ * CHUNK_F),                      \
                            chunk_src(wsrc, chunk + NSTAGE),                    \
                            CHUNK_BYTES, fullb + s_ * 8, MC_MASK);              \
            }                                                                   \
        }                                                                       \
        chunk++;                                                                \
    } while (0)

    for (int t = 0; t < T_; t++) {
        const int c0 = tid * 2;

        // ===== Layer 1: y1 = relu(h @ W1 + b1), K=256 (16 chunks x 16k) =====
        {
            u64 a0 = 0, a1 = 0;
            for (int j = 0; j < 16; j++) {
                const int s = chunk & (NSTAGE - 1);
                mbar_wait_parity(fullb + s * 8, (chunk >> 2) & 1);
                const float* wb = wbuf + s * CHUNK_F;
#pragma unroll
                for (int kk = 0; kk < 16; kk++) {
                    const int k = j * 16 + kk;
                    u64 r = *(const u64*)(hT + k * 2);           // broadcast
                    float2 w = *(const float2*)(wb + kk * W1_ + c0);
                    a0 = fma2(r, dup2(w.x), a0);
                    a1 = fma2(r, dup2(w.y), a1);
                }
                CHUNK_BOOKKEEP();
            }
            float v0, v1;
            const float bb0 = bs1[c0], bb1 = bs1[c0 + 1];
            unpack2(a0, v0, v1);
            *(float2*)(y1T + c0 * 2) =
                make_float2(fmaxf(v0 + bb0, 0.f), fmaxf(v1 + bb0, 0.f));
            unpack2(a1, v0, v1);
            *(float2*)(y1T + (c0 + 1) * 2) =
                make_float2(fmaxf(v0 + bb1, 0.f), fmaxf(v1 + bb1, 0.f));
        }
        __syncthreads();

        // ===== Layer 2: y2 = relu(y1 @ W2 + b2), K=512 (32 chunks x 16k) ====
        {
            u64 a0 = 0, a1 = 0;
            for (int j = 0; j < 32; j++) {
                const int s = chunk & (NSTAGE - 1);
                mbar_wait_parity(fullb + s * 8, (chunk >> 2) & 1);
                const float* wb = wbuf + s * CHUNK_F;
#pragma unroll
                for (int kk = 0; kk < 16; kk++) {
                    const int k = j * 16 + kk;
                    u64 r = *(const u64*)(y1T + k * 2);
                    float2 w = *(const float2*)(wb + kk * W2_ + c0);
                    a0 = fma2(r, dup2(w.x), a0);
                    a1 = fma2(r, dup2(w.y), a1);
                }
                CHUNK_BOOKKEEP();
            }
            float v0, v1;
            const float bb0 = bs2[c0], bb1 = bs2[c0 + 1];
            unpack2(a0, v0, v1);
            *(float2*)(y2T + c0 * 2) =
                make_float2(fmaxf(v0 + bb0, 0.f), fmaxf(v1 + bb0, 0.f));
            unpack2(a1, v0, v1);
            *(float2*)(y2T + (c0 + 1) * 2) =
                make_float2(fmaxf(v0 + bb1, 0.f), fmaxf(v1 + bb1, 0.f));
        }
        __syncthreads();

        // ===== Layer 3: h = tanh(y2 @ W3 + b3 + xin_t), K=512 (16 x 32k) ====
        {
            const int c = tid;   // one column per thread (N=256)
            u64 ae = 0, ao = 0;  // even/odd split for ILP
            for (int j = 0; j < 16; j++) {
                const int s = chunk & (NSTAGE - 1);
                mbar_wait_parity(fullb + s * 8, (chunk >> 2) & 1);
                const float* wb = wbuf + s * CHUNK_F;
#pragma unroll
                for (int kk = 0; kk < 32; kk += 2) {
                    const int k = j * 32 + kk;
                    u64 r0 = *(const u64*)(y2T + k * 2);
                    u64 r1 = *(const u64*)(y2T + (k + 1) * 2);
                    ae = fma2(r0, dup2(wb[kk * H_ + c]),       ae);
                    ao = fma2(r1, dup2(wb[(kk + 1) * H_ + c]), ao);
                }
                CHUNK_BOOKKEEP();
            }
            float e0, e1, o0, o1;
            unpack2(ae, e0, e1); unpack2(ao, o0, o1);
            const float bb = bs3[c];
            const float* xr = xin + (size_t)t * B_ * H_ + (size_t)b0 * H_ + c;
            float*       hr = hs  + (size_t)t * B_ * H_ + (size_t)b0 * H_ + c;
            float v0 = tanhf(e0 + o0 + bb + xr[0 * H_]);
            float v1 = tanhf(e1 + o1 + bb + xr[1 * H_]);
            hr[0 * H_] = v0; hr[1 * H_] = v1;
            *(float2*)(hT + c * 2) = make_float2(v0, v1);
        }
        __syncthreads();    // hT ready before next step's layer 1
    }

    CLUSTER_SYNC();          // no CTA exits while peers' multicasts may target it
#undef CHUNK_BOOKKEEP
}

// ---------------------------------------------------------------------------
// Phase C reduction: online softmax over T (axis 0) + weighted sum of hs.
// ---------------------------------------------------------------------------
__global__ void attn_reduce_kernel(const float* __restrict__ aw,
                                   const float* __restrict__ hs,
                                   float* __restrict__ out)
{
    const int b = blockIdx.x;
    const int h = threadIdx.x;
    float m = -1e30f, s = 0.f, acc = 0.f;
    for (int t = 0; t < T_; t++) {
        size_t idx = ((size_t)t * B_ + b) * H_ + h;
        float a  = aw[idx];
        float hv = hs[idx];
        if (a > m) {
            float c = __expf(m - a);
            s   = s * c + 1.f;
            acc = acc * c + hv;
            m   = a;
        } else {
            float e = __expf(a - m);
            s   += e;
            acc += e * hv;
        }
    }
    out[(size_t)b * H_ + h] = acc / s;
}

// ---------------------------------------------------------------------------
// Launch
// ---------------------------------------------------------------------------
extern "C" void kernel_launch(void* const* d_in, const int* in_sizes, int n_in,
                              void* d_out, int out_size)
{
    const float* x     = (const float*)d_in[0];
    const float* h_w1  = (const float*)d_in[1];
    const float* h_b1  = (const float*)d_in[2];
    const float* h_w2  = (const float*)d_in[3];
    const float* h_b2  = (const float*)d_in[4];
    const float* h_w3  = (const float*)d_in[5];
    const float* h_b3  = (const float*)d_in[6];
    const float* i_w1  = (const float*)d_in[7];
    const float* i_b1  = (const float*)d_in[8];
    const float* i_w2  = (const float*)d_in[9];
    const float* i_b2  = (const float*)d_in[10];
    const float* i_w3  = (const float*)d_in[11];
    const float* i_b3  = (const float*)d_in[12];
    const float* att_w = (const float*)d_in[13];
    const float* att_b = (const float*)d_in[14];
    float* out = (float*)d_out;

    float *t1, *t2, *xin, *hs;
    cudaGetSymbolAddress((void**)&t1,  g_t1);
    cudaGetSymbolAddress((void**)&t2,  g_t2);
    cudaGetSymbolAddress((void**)&xin, g_xin);
    cudaGetSymbolAddress((void**)&hs,  g_hs);
    float* aw = t1;   // reuse t1 for attention logits in Phase C

    // ---------------- Phase A: input MLP over all B*T rows ----------------
    gemm_kernel<1,false,false><<<dim3(W1_/128, BT_/128), 256>>>(
        x,  i_w1, i_b1, nullptr, t1,  BT_, W1_, IN_);
    gemm_kernel<1,false,false><<<dim3(W2_/128, BT_/128), 256>>>(
        t1, i_w2, i_b2, nullptr, t2,  BT_, W2_, W1_);
    gemm_kernel<0,true ,false><<<dim3(H_/128, BT_/128), 256>>>(
        t2, i_w3, i_b3, nullptr, xin, BT_, H_, W2_);

    // ---------------- Phase B: persistent recurrence (ONE launch) ---------
    cudaFuncSetAttribute(recurrence_kernel,
                         cudaFuncAttributeMaxDynamicSharedMemorySize, SMEM_BYTES);
    recurrence_kernel<<<128, 256, SMEM_BYTES>>>(
        h_w1, h_b1, h_w2, h_b2, h_w3, h_b3, xin, hs);

    // ---------------- Phase C: attention pooling --------------------------
    gemm_kernel<2,false,false><<<dim3(H_/128, BT_/128), 256>>>(
        hs, att_w, att_b, nullptr, aw, BT_, H_, H_);
    attn_reduce_kernel<<<B_, H_>>>(aw, hs, out);
}